// round 1
// baseline (speedup 1.0000x reference)
#include <cuda_runtime.h>
#include <math.h>

// Problem constants
#define Bb 16
#define Ll 128
#define Dd 512
#define Ff 1024
#define Kk 16
#define Mm (Bb*Ll)   // 2048

// -------- device scratch (no allocations allowed) --------
__device__ __align__(16) float g_c1[Ll*Kk];
__device__ __align__(16) float g_c2[Ll*Kk];
__device__ __align__(16) float g_c3[Ll*Kk];
__device__ __align__(16) float g_Gg[256*Ff];
__device__ __align__(16) float g_Gu[256*Ff];
__device__ __align__(16) float g_Gd[256*Dd];
__device__ __align__(16) float g_ing[Ll*Ff];   // 1/max(norm_gate,eps)
__device__ __align__(16) float g_inu[Ll*Ff];
__device__ __align__(16) float g_ind[Ll*Dd];
__device__ __align__(16) float g_U[Mm*Ff];
__device__ __align__(16) float g_V[Mm*Ff];
__device__ __align__(16) float g_H[Mm*Ff];
__device__ __align__(16) float g_O[Mm*Dd];

// ---------------- softmax over K=16 per token, 3 coef sets ----------------
__global__ void softmax_kernel(const float* __restrict__ t1,
                               const float* __restrict__ t2,
                               const float* __restrict__ t3) {
    const float* src = (blockIdx.x == 0) ? t1 : (blockIdx.x == 1) ? t2 : t3;
    float* dst = (blockIdx.x == 0) ? g_c1 : (blockIdx.x == 1) ? g_c2 : g_c3;
    int l = threadIdx.x;  // 128 threads
    float v[16];
    float mx = -1e30f;
#pragma unroll
    for (int k = 0; k < 16; k++) { v[k] = src[l*16 + k]; mx = fmaxf(mx, v[k]); }
    float s = 0.f;
#pragma unroll
    for (int k = 0; k < 16; k++) { v[k] = expf(v[k] - mx); s += v[k]; }
    float inv = 1.f / s;
#pragma unroll
    for (int k = 0; k < 16; k++) dst[l*16 + k] = v[k] * inv;
}

// ---------------- Gram tensors: G[k1*16+k2][c] = sum_r W[k1,r,c]*W[k2,r,c] ----------------
// blockIdx.y selects weight (0=gate R=512,C=1024; 1=up; 2=down R=1024,C=512)
// blockIdx.x: tile of 32 columns. 256 threads.
__global__ void gram_kernel(const float* __restrict__ Wg,
                            const float* __restrict__ Wu,
                            const float* __restrict__ Wd) {
    int w = blockIdx.y;
    const float* W; float* G; int R, C;
    if (w == 0)      { W = Wg; G = g_Gg; R = Dd; C = Ff; }
    else if (w == 1) { W = Wu; G = g_Gu; R = Dd; C = Ff; }
    else             { W = Wd; G = g_Gd; R = Ff; C = Dd; }
    int c0 = blockIdx.x * 32;
    if (c0 >= C) return;

    __shared__ __align__(16) float s[16][8][32];  // [k][r][c] 16KB
    int t = threadIdx.x;
    int cc = t & 31;
    int pg = t >> 5;          // 0..7 : owns k1 in {2pg, 2pg+1}, all k2
    float acc[32];
#pragma unroll
    for (int i = 0; i < 32; i++) acc[i] = 0.f;

    for (int r0 = 0; r0 < R; r0 += 8) {
        __syncthreads();
#pragma unroll
        for (int j = 0; j < 16; j++) {
            int idx = j * 256 + t;
            int lc = idx & 31, rr = (idx >> 5) & 7, k = idx >> 8;
            s[k][rr][lc] = W[(size_t)k * R * C + (size_t)(r0 + rr) * C + c0 + lc];
        }
        __syncthreads();
#pragma unroll
        for (int rr = 0; rr < 8; rr++) {
            float wv[16];
#pragma unroll
            for (int k = 0; k < 16; k++) wv[k] = s[k][rr][cc];
            float a0 = s[(pg << 1) + 0][rr][cc];
            float a1 = s[(pg << 1) + 1][rr][cc];
#pragma unroll
            for (int pp = 0; pp < 16; pp++) acc[pp]      += a0 * wv[pp];
#pragma unroll
            for (int pp = 0; pp < 16; pp++) acc[16 + pp] += a1 * wv[pp];
        }
    }
#pragma unroll
    for (int pp = 0; pp < 32; pp++) {
        int p = ((pg << 1) + (pp >> 4)) * 16 + (pp & 15);
        G[(size_t)p * C + c0 + cc] = acc[pp];
    }
}

// ---------------- inverse norms: 1/max(sqrt(sum_{k1,k2} c c G), eps) ----------------
// grid (C/128, L, 3), block 128
__global__ void norm_kernel() {
    int w = blockIdx.z;
    int l = blockIdx.y;
    const float* G; const float* coef; float* out; int C;
    if (w == 0)      { G = g_Gg; coef = g_c1; out = g_ing; C = Ff; }
    else if (w == 1) { G = g_Gu; coef = g_c2; out = g_inu; C = Ff; }
    else             { G = g_Gd; coef = g_c3; out = g_ind; C = Dd; }
    int c = blockIdx.x * 128 + threadIdx.x;
    if (c >= C) return;

    __shared__ float w2[256];
    if (threadIdx.x < 16) {
        float ci = coef[l*16 + threadIdx.x];
        // also stage coef row via first 16 threads, then products
        for (int k2 = 0; k2 < 16; k2++)
            w2[threadIdx.x * 16 + k2] = ci * coef[l*16 + k2];
    }
    __syncthreads();
    float acc = 0.f;
#pragma unroll 8
    for (int p = 0; p < 256; p++)
        acc += w2[p] * G[(size_t)p * C + c];
    out[l*C + c] = 1.f / fmaxf(sqrtf(fmaxf(acc, 0.f)), 1e-12f);
}

// ---------------- GEMM: Cout[M,N] = A_eff[M, 16*Ka] @ Bw[16*Ka, N] ----------------
// A_eff[m, k*Ka + d] = coef[(m&127)*16 + k] * A[m, d]
// sel: 0 -> A=x, coef=c1, out=U ; 1 -> A=x, coef=c2, out=V ; 2 -> A=H, coef=c3, out=O
// BM=BN=64, BK=16, 128 threads, per-thread 4x8.
__global__ void gemm_kernel(const float* __restrict__ Aext,
                            const float* __restrict__ Bw,
                            int sel, int Ka, int lg2Ka, int N) {
    const float* A    = (sel == 2) ? g_H : Aext;
    const float* coef = (sel == 0) ? g_c1 : (sel == 1) ? g_c2 : g_c3;
    float* Cout       = (sel == 0) ? g_U  : (sel == 1) ? g_V  : g_O;

    __shared__ __align__(16) float As[16][68];  // transposed A tile, padded
    __shared__ __align__(16) float Bs[16][64];

    int t = threadIdx.x;          // 128
    int m0 = blockIdx.y * 64;
    int n0 = blockIdx.x * 64;
    int rg = t >> 3;              // 0..15 row group (4 rows each)
    int cg = t & 7;               // 0..7  col group (8 cols each)

    float acc[4][8];
#pragma unroll
    for (int i = 0; i < 4; i++)
#pragma unroll
        for (int j = 0; j < 8; j++) acc[i][j] = 0.f;

    int Kdim = Ka << 4;
    int kmask = Ka - 1;

    for (int kt = 0; kt < Kdim; kt += 16) {
        int kseg  = kt >> lg2Ka;
        int kbase = kt & kmask;
#pragma unroll
        for (int j = 0; j < 2; j++) {
            int i = t * 2 + j;
            // A tile: 64 rows x 16 cols
            int ar = i >> 2, ac = (i & 3) * 4;
            float4 av = *(const float4*)(A + (size_t)(m0 + ar) * Ka + kbase + ac);
            float sc = coef[((m0 + ar) & 127) * 16 + kseg];
            As[ac + 0][ar] = av.x * sc;
            As[ac + 1][ar] = av.y * sc;
            As[ac + 2][ar] = av.z * sc;
            As[ac + 3][ar] = av.w * sc;
            // B tile: 16 rows x 64 cols
            int br = i >> 4, bc = (i & 15) * 4;
            float4 bv = *(const float4*)(Bw + (size_t)(kt + br) * N + n0 + bc);
            *(float4*)(&Bs[br][bc]) = bv;
        }
        __syncthreads();
#pragma unroll
        for (int kk = 0; kk < 16; kk++) {
            float4 a  = *(const float4*)(&As[kk][rg * 4]);
            float4 b0 = *(const float4*)(&Bs[kk][cg * 8]);
            float4 b1 = *(const float4*)(&Bs[kk][cg * 8 + 4]);
            float av[4] = {a.x, a.y, a.z, a.w};
            float bv[8] = {b0.x, b0.y, b0.z, b0.w, b1.x, b1.y, b1.z, b1.w};
#pragma unroll
            for (int i = 0; i < 4; i++)
#pragma unroll
                for (int j = 0; j < 8; j++)
                    acc[i][j] += av[i] * bv[j];
        }
        __syncthreads();
    }

#pragma unroll
    for (int i = 0; i < 4; i++) {
        float4 o0 = make_float4(acc[i][0], acc[i][1], acc[i][2], acc[i][3]);
        float4 o1 = make_float4(acc[i][4], acc[i][5], acc[i][6], acc[i][7]);
        size_t off = (size_t)(m0 + rg * 4 + i) * N + n0 + cg * 8;
        *(float4*)(Cout + off)     = o0;
        *(float4*)(Cout + off + 4) = o1;
    }
}

// ---------------- elementwise: h = silu(vs*v) * (us*u), with norm application ----------------
__global__ void h_kernel(const float* __restrict__ usp, const float* __restrict__ vsp) {
    const float SQRT_D = 22.62741699796952f;  // sqrt(512)
    int i4 = blockIdx.x * blockDim.x + threadIdx.x;
    if (i4 >= Mm * Ff / 4) return;
    int m  = i4 >> 8;           // Ff/4 = 256 float4 per row
    int f  = (i4 & 255) * 4;
    int l  = m & 127;

    float4 u  = *(const float4*)(g_U   + (size_t)m * Ff + f);
    float4 v  = *(const float4*)(g_V   + (size_t)m * Ff + f);
    float4 ig = *(const float4*)(g_ing + (size_t)l * Ff + f);
    float4 iu = *(const float4*)(g_inu + (size_t)l * Ff + f);
    float4 us = *(const float4*)(usp + f);
    float4 vs = *(const float4*)(vsp + f);

    float4 h;
    {
        float uu = u.x * ig.x, vv = v.x * iu.x;
        float z = fabsf(vs.x) * SQRT_D * vv;
        h.x = (z / (1.f + expf(-z))) * (fabsf(us.x) * uu);
    }
    {
        float uu = u.y * ig.y, vv = v.y * iu.y;
        float z = fabsf(vs.y) * SQRT_D * vv;
        h.y = (z / (1.f + expf(-z))) * (fabsf(us.y) * uu);
    }
    {
        float uu = u.z * ig.z, vv = v.z * iu.z;
        float z = fabsf(vs.z) * SQRT_D * vv;
        h.z = (z / (1.f + expf(-z))) * (fabsf(us.z) * uu);
    }
    {
        float uu = u.w * ig.w, vv = v.w * iu.w;
        float z = fabsf(vs.w) * SQRT_D * vv;
        h.w = (z / (1.f + expf(-z))) * (fabsf(us.w) * uu);
    }
    *(float4*)(g_H + (size_t)m * Ff + f) = h;
}

// ---------------- final: apply down-norm, then row L2 normalize over D ----------------
__global__ void out_kernel(float* __restrict__ out) {
    int m = blockIdx.x;           // 2048
    int t = threadIdx.x;          // 128, each 4 floats -> D=512
    int l = m & 127;

    float4 o  = *(const float4*)(g_O   + (size_t)m * Dd + t * 4);
    float4 iv = *(const float4*)(g_ind + (size_t)l * Dd + t * 4);
    o.x *= iv.x; o.y *= iv.y; o.z *= iv.z; o.w *= iv.w;

    float ss = o.x*o.x + o.y*o.y + o.z*o.z + o.w*o.w;
#pragma unroll
    for (int off = 16; off > 0; off >>= 1)
        ss += __shfl_xor_sync(0xffffffffu, ss, off);

    __shared__ float ws[4];
    if ((t & 31) == 0) ws[t >> 5] = ss;
    __syncthreads();
    float tot = ws[0] + ws[1] + ws[2] + ws[3];
    float sc = 1.f / fmaxf(sqrtf(tot), 1e-12f);

    o.x *= sc; o.y *= sc; o.z *= sc; o.w *= sc;
    *(float4*)(out + (size_t)m * Dd + t * 4) = o;
}

// ---------------- launch ----------------
extern "C" void kernel_launch(void* const* d_in, const int* in_sizes, int n_in,
                              void* d_out, int out_size) {
    const float* x   = (const float*)d_in[0];
    const float* Wg  = (const float*)d_in[1];
    const float* Wu  = (const float*)d_in[2];
    const float* Wd  = (const float*)d_in[3];
    const float* t1  = (const float*)d_in[4];
    const float* t2  = (const float*)d_in[5];
    const float* t3  = (const float*)d_in[6];
    const float* usp = (const float*)d_in[7];
    const float* vsp = (const float*)d_in[8];
    float* out = (float*)d_out;

    softmax_kernel<<<3, 128>>>(t1, t2, t3);
    gram_kernel<<<dim3(32, 3), 256>>>(Wg, Wu, Wd);
    norm_kernel<<<dim3(8, Ll, 3), 128>>>();

    // U = (c1 . x) @ Wg   [2048,1024]
    gemm_kernel<<<dim3(16, 32), 128>>>(x, Wg, 0, 512, 9, 1024);
    // V = (c2 . x) @ Wu
    gemm_kernel<<<dim3(16, 32), 128>>>(x, Wu, 1, 512, 9, 1024);
    // h = silu(vs*v) * (us*u)
    h_kernel<<<2048, 256>>>(usp, vsp);
    // O = (c3 . h) @ Wd   [2048,512]
    gemm_kernel<<<dim3(8, 32), 128>>>(nullptr, Wd, 2, 1024, 10, 512);
    // apply down norm + final row L2 normalize
    out_kernel<<<2048, 128>>>(out);
}

// round 6
// speedup vs baseline: 3.3071x; 3.3071x over previous
#include <cuda_runtime.h>
#include <cuda_bf16.h>
#include <math.h>
#include <stdint.h>

// Problem constants
#define Bb 16
#define Ll 128
#define Dd 512
#define Ff 1024
#define Mm 2048

// -------- device scratch (same footprint class as the passing R1 kernel) --------
__device__ __align__(16) float g_c1[Ll*16];
__device__ __align__(16) float g_c2[Ll*16];
__device__ __align__(16) float g_c3[Ll*16];
__device__ __align__(16) float g_Gg[256*Ff];
__device__ __align__(16) float g_Gu[256*Ff];
__device__ __align__(16) float g_Gd[256*Dd];
__device__ __align__(16) float g_ing[Ll*Ff];
__device__ __align__(16) float g_inu[Ll*Ff];
__device__ __align__(16) float g_ind[Ll*Dd];
__device__ __align__(16) float g_U[Mm*Ff];
__device__ __align__(16) float g_V[Mm*Ff];
__device__ __align__(16) float g_H[Mm*Ff];
__device__ __align__(16) float g_O[Mm*Dd];

// ---------------- PTX helpers ----------------
__device__ __forceinline__ uint32_t smem_u32(const void* p) {
    uint32_t a;
    asm("{ .reg .u64 t; cvta.to.shared.u64 t, %1; cvt.u32.u64 %0, t; }" : "=r"(a) : "l"(p));
    return a;
}
__device__ __forceinline__ void ldsm4(uint32_t* r, uint32_t addr) {
    asm volatile("ldmatrix.sync.aligned.m8n8.x4.shared.b16 {%0,%1,%2,%3}, [%4];"
        : "=r"(r[0]), "=r"(r[1]), "=r"(r[2]), "=r"(r[3]) : "r"(addr));
}
__device__ __forceinline__ void ldsm4t(uint32_t* r, uint32_t addr) {
    asm volatile("ldmatrix.sync.aligned.m8n8.x4.trans.shared.b16 {%0,%1,%2,%3}, [%4];"
        : "=r"(r[0]), "=r"(r[1]), "=r"(r[2]), "=r"(r[3]) : "r"(addr));
}
__device__ __forceinline__ void mma16816(float* c, const uint32_t* a, const uint32_t* b) {
    asm volatile("mma.sync.aligned.m16n8k16.row.col.f32.bf16.bf16.f32 "
        "{%0,%1,%2,%3}, {%4,%5,%6,%7}, {%8,%9}, {%0,%1,%2,%3};"
        : "+f"(c[0]), "+f"(c[1]), "+f"(c[2]), "+f"(c[3])
        : "r"(a[0]), "r"(a[1]), "r"(a[2]), "r"(a[3]), "r"(b[0]), "r"(b[1]));
}
__device__ __forceinline__ void sts16(uint32_t addr, uint4 v) {
    asm volatile("st.shared.v4.b32 [%0], {%1,%2,%3,%4};" ::
        "r"(addr), "r"(v.x), "r"(v.y), "r"(v.z), "r"(v.w) : "memory");
}
__device__ __forceinline__ void sts8(uint32_t addr, uint32_t x, uint32_t y) {
    asm volatile("st.shared.v2.b32 [%0], {%1,%2};" :: "r"(addr), "r"(x), "r"(y) : "memory");
}

// split float4 -> 4 bf16 hi (8B) + 4 bf16 lo (8B), store to smem
__device__ __forceinline__ void cvt_store4(float4 v, uint32_t hiAddr, uint32_t loAddr) {
    __nv_bfloat162 h0 = __float22bfloat162_rn(make_float2(v.x, v.y));
    __nv_bfloat162 h1 = __float22bfloat162_rn(make_float2(v.z, v.w));
    float2 f0 = __bfloat1622float2(h0);
    float2 f1 = __bfloat1622float2(h1);
    __nv_bfloat162 l0 = __float22bfloat162_rn(make_float2(v.x - f0.x, v.y - f0.y));
    __nv_bfloat162 l1 = __float22bfloat162_rn(make_float2(v.z - f1.x, v.w - f1.y));
    sts8(hiAddr, *(uint32_t*)&h0, *(uint32_t*)&h1);
    sts8(loAddr, *(uint32_t*)&l0, *(uint32_t*)&l1);
}
// scaled variant for A (8 floats)
__device__ __forceinline__ void cvt_store8s(float4 va, float4 vb, float sc,
                                            uint32_t hiAddr, uint32_t loAddr) {
    va.x *= sc; va.y *= sc; va.z *= sc; va.w *= sc;
    vb.x *= sc; vb.y *= sc; vb.z *= sc; vb.w *= sc;
    __nv_bfloat162 h0 = __float22bfloat162_rn(make_float2(va.x, va.y));
    __nv_bfloat162 h1 = __float22bfloat162_rn(make_float2(va.z, va.w));
    __nv_bfloat162 h2 = __float22bfloat162_rn(make_float2(vb.x, vb.y));
    __nv_bfloat162 h3 = __float22bfloat162_rn(make_float2(vb.z, vb.w));
    float2 f0 = __bfloat1622float2(h0);
    float2 f1 = __bfloat1622float2(h1);
    float2 f2 = __bfloat1622float2(h2);
    float2 f3 = __bfloat1622float2(h3);
    __nv_bfloat162 l0 = __float22bfloat162_rn(make_float2(va.x - f0.x, va.y - f0.y));
    __nv_bfloat162 l1 = __float22bfloat162_rn(make_float2(va.z - f1.x, va.w - f1.y));
    __nv_bfloat162 l2 = __float22bfloat162_rn(make_float2(vb.x - f2.x, vb.y - f2.y));
    __nv_bfloat162 l3 = __float22bfloat162_rn(make_float2(vb.z - f3.x, vb.w - f3.y));
    sts16(hiAddr, make_uint4(*(uint32_t*)&h0, *(uint32_t*)&h1, *(uint32_t*)&h2, *(uint32_t*)&h3));
    sts16(loAddr, make_uint4(*(uint32_t*)&l0, *(uint32_t*)&l1, *(uint32_t*)&l2, *(uint32_t*)&l3));
}

// ---------------- softmax ----------------
__global__ void softmax_kernel(const float* __restrict__ t1,
                               const float* __restrict__ t2,
                               const float* __restrict__ t3) {
    const float* src = (blockIdx.x == 0) ? t1 : (blockIdx.x == 1) ? t2 : t3;
    float* dst = (blockIdx.x == 0) ? g_c1 : (blockIdx.x == 1) ? g_c2 : g_c3;
    int l = threadIdx.x;
    float v[16];
    float mx = -1e30f;
#pragma unroll
    for (int k = 0; k < 16; k++) { v[k] = src[l*16 + k]; mx = fmaxf(mx, v[k]); }
    float s = 0.f;
#pragma unroll
    for (int k = 0; k < 16; k++) { v[k] = expf(v[k] - mx); s += v[k]; }
    float inv = 1.f / s;
#pragma unroll
    for (int k = 0; k < 16; k++) dst[l*16 + k] = v[k] * inv;
}

// ---------------- Gram ----------------
__global__ void gram_kernel(const float* __restrict__ Wg,
                            const float* __restrict__ Wu,
                            const float* __restrict__ Wd) {
    int w = blockIdx.y;
    const float* W; float* G; int R, C;
    if (w == 0)      { W = Wg; G = g_Gg; R = Dd; C = Ff; }
    else if (w == 1) { W = Wu; G = g_Gu; R = Dd; C = Ff; }
    else             { W = Wd; G = g_Gd; R = Ff; C = Dd; }
    int c0 = blockIdx.x * 32;
    if (c0 >= C) return;

    __shared__ __align__(16) float s[16][8][32];
    int t = threadIdx.x;
    int cc = t & 31;
    int pg = t >> 5;
    float acc[32];
#pragma unroll
    for (int i = 0; i < 32; i++) acc[i] = 0.f;

    for (int r0 = 0; r0 < R; r0 += 8) {
        __syncthreads();
#pragma unroll
        for (int j = 0; j < 16; j++) {
            int idx = j * 256 + t;
            int lc = idx & 31, rr = (idx >> 5) & 7, k = idx >> 8;
            s[k][rr][lc] = W[(size_t)k * R * C + (size_t)(r0 + rr) * C + c0 + lc];
        }
        __syncthreads();
#pragma unroll
        for (int rr = 0; rr < 8; rr++) {
            float wv[16];
#pragma unroll
            for (int k = 0; k < 16; k++) wv[k] = s[k][rr][cc];
            float a0 = s[(pg << 1) + 0][rr][cc];
            float a1 = s[(pg << 1) + 1][rr][cc];
#pragma unroll
            for (int pp = 0; pp < 16; pp++) acc[pp]      += a0 * wv[pp];
#pragma unroll
            for (int pp = 0; pp < 16; pp++) acc[16 + pp] += a1 * wv[pp];
        }
    }
#pragma unroll
    for (int pp = 0; pp < 32; pp++) {
        int p = ((pg << 1) + (pp >> 4)) * 16 + (pp & 15);
        G[(size_t)p * C + c0 + cc] = acc[pp];
    }
}

// ---------------- inverse norms ----------------
__global__ void norm_kernel() {
    int w = blockIdx.z;
    int l = blockIdx.y;
    const float* G; const float* coef; float* out; int C;
    if (w == 0)      { G = g_Gg; coef = g_c1; out = g_ing; C = Ff; }
    else if (w == 1) { G = g_Gu; coef = g_c2; out = g_inu; C = Ff; }
    else             { G = g_Gd; coef = g_c3; out = g_ind; C = Dd; }
    int c = blockIdx.x * 128 + threadIdx.x;
    if (c >= C) return;

    __shared__ float w2[256];
    if (threadIdx.x < 16) {
        float ci = coef[l*16 + threadIdx.x];
        for (int k2 = 0; k2 < 16; k2++)
            w2[threadIdx.x * 16 + k2] = ci * coef[l*16 + k2];
    }
    __syncthreads();
    float acc = 0.f;
#pragma unroll 8
    for (int p = 0; p < 256; p++)
        acc += w2[p] * G[(size_t)p * C + c];
    out[l*C + c] = 1.f / fmaxf(sqrtf(fmaxf(acc, 0.f)), 1e-12f);
}

// ---------------- split-bf16 HMMA GEMM, in-kernel B conversion ----------------
// C[M=2048, N] = A_eff @ Bw where A_eff[m, kseg*Ka + d] = coef[(m&127)*16+kseg]*A[m,d],
// Bw = fp32 weight basis viewed as [Ktot, N] row-major (n-contiguous).
// BM=128, BK=32, 256 threads, 8 warps (2m x 4n).
// A smem: [m][k] 80B rows (hi & lo). B smem: [k][n] k-major rows, padded stride (hi & lo).
template<int BN>
__global__ void __launch_bounds__(256, 1) gemm3(
    const float* __restrict__ Aext, const float* __restrict__ Bw, int sel,
    int Ka, int ksegShift, int Ktot, int Nglob)
{
    constexpr int WN = BN / 4;
    constexpr int NF = WN / 8;
    constexpr int AMB = 128 * 80;             // one A matrix
    constexpr int BSTRIDE = BN * 2 + 16;      // 272 / 144 (odd multiple of 16)
    constexpr int BMB = 32 * BSTRIDE;
    constexpr int QPT = (BN == 128 ? 4 : 2);  // float4 quads per thread for B

    __shared__ __align__(128) char smem_raw[2 * AMB + 2 * BMB];
    uint32_t sA_hi = smem_u32(smem_raw);
    uint32_t sA_lo = sA_hi + AMB;
    uint32_t sB_hi = sA_hi + 2 * AMB;
    uint32_t sB_lo = sB_hi + BMB;

    const float* coef; float* Cout; const float* Ap;
    if (sel == 0)      { Ap = Aext; coef = g_c1; Cout = g_U; }
    else if (sel == 1) { Ap = Aext; coef = g_c2; Cout = g_V; }
    else               { Ap = g_H;  coef = g_c3; Cout = g_O; }

    int t = threadIdx.x, lane = t & 31, warp = t >> 5;
    int wm = warp & 1, wn = warp >> 1;
    int m0 = blockIdx.y * 128, n0 = blockIdx.x * BN;

    // A staging: one thread per (row, 16-float half)
    int arow = t >> 1, ahalf = t & 1;
    const float* aRow = Ap + (size_t)(m0 + arow) * Ka;
    const float* crow = coef + ((m0 + arow) & 127) * 16;
    uint32_t aDstHi = sA_hi + (uint32_t)arow * 80 + ahalf * 32;
    uint32_t aDstLo = sA_lo + (uint32_t)arow * 80 + ahalf * 32;

    // B staging: krow = t>>3 (32 rows), 8 threads/row, QPT float4 each
    int krow = t >> 3;
    int qbase = (t & 7) * QPT;
    const float* bRowBase = Bw + (size_t)krow * Nglob + n0 + qbase * 4;
    uint32_t bDstHi = sB_hi + (uint32_t)krow * BSTRIDE + qbase * 8;
    uint32_t bDstLo = sB_lo + (uint32_t)krow * BSTRIDE + qbase * 8;

    float acc[4][NF][4];
#pragma unroll
    for (int f = 0; f < 4; f++)
#pragma unroll
        for (int g = 0; g < NF; g++)
#pragma unroll
            for (int j = 0; j < 4; j++) acc[f][g][j] = 0.f;

    // stage iter 0 into registers
    float4 aReg[4];
    float4 bReg[QPT];
    float  aSc = crow[0];
#pragma unroll
    for (int j = 0; j < 4; j++)
        aReg[j] = *(const float4*)(aRow + ahalf * 16 + j * 4);
#pragma unroll
    for (int j = 0; j < QPT; j++)
        bReg[j] = *(const float4*)(bRowBase + j * 4);

    int nit = Ktot >> 5;
    for (int it = 0; it < nit; it++) {
        __syncthreads();   // previous iter's MMAs done reading smem
        cvt_store8s(aReg[0], aReg[1], aSc, aDstHi, aDstLo);
        cvt_store8s(aReg[2], aReg[3], aSc, aDstHi + 16, aDstLo + 16);
#pragma unroll
        for (int j = 0; j < QPT; j++)
            cvt_store4(bReg[j], bDstHi + j * 8, bDstLo + j * 8);
        __syncthreads();   // tile visible

        if (it + 1 < nit) {
            int ktn = (it + 1) << 5;
            int kseg = ktn >> ksegShift;
            int kbase = ktn & (Ka - 1);
            aSc = crow[kseg];
#pragma unroll
            for (int j = 0; j < 4; j++)
                aReg[j] = *(const float4*)(aRow + kbase + ahalf * 16 + j * 4);
            const float* br = bRowBase + (size_t)ktn * Nglob;
#pragma unroll
            for (int j = 0; j < QPT; j++)
                bReg[j] = *(const float4*)(br + j * 4);
        }

#pragma unroll
        for (int ks = 0; ks < 2; ks++) {
            // A fragments (non-trans ldmatrix)
            uint32_t acolB = (uint32_t)ks * 32 + ((lane >> 4) & 1) * 16;
            uint32_t AH[4][4], AL[4][4];
#pragma unroll
            for (int f = 0; f < 4; f++) {
                uint32_t roff = (uint32_t)(wm * 64 + f * 16 + (lane & 15)) * 80 + acolB;
                ldsm4(AH[f], sA_hi + roff);
                ldsm4(AL[f], sA_lo + roff);
            }
            // B fragments (trans ldmatrix from k-major tile)
            uint32_t BH[NF][2], BL[NF][2];
            uint32_t brow = (uint32_t)(ks * 16 + (lane & 15)) * BSTRIDE;
#pragma unroll
            for (int j = 0; j < NF / 2; j++) {
                uint32_t coff = (uint32_t)(wn * WN + j * 16 + ((lane >> 4) & 1) * 8) * 2;
                uint32_t r[4];
                ldsm4t(r, sB_hi + brow + coff);
                BH[2*j][0] = r[0]; BH[2*j][1] = r[1];
                BH[2*j+1][0] = r[2]; BH[2*j+1][1] = r[3];
                ldsm4t(r, sB_lo + brow + coff);
                BL[2*j][0] = r[0]; BL[2*j][1] = r[1];
                BL[2*j+1][0] = r[2]; BL[2*j+1][1] = r[3];
            }
#pragma unroll
            for (int f = 0; f < 4; f++)
#pragma unroll
                for (int g = 0; g < NF; g++) {
                    mma16816(acc[f][g], AH[f], BH[g]);
                    mma16816(acc[f][g], AL[f], BH[g]);
                    mma16816(acc[f][g], AH[f], BL[g]);
                }
        }
    }

    // epilogue
#pragma unroll
    for (int f = 0; f < 4; f++) {
#pragma unroll
        for (int g = 0; g < NF; g++) {
            int r0 = m0 + wm * 64 + f * 16 + (lane >> 2);
            int col = n0 + wn * WN + g * 8 + (lane & 3) * 2;
            float* p = Cout + (size_t)r0 * Nglob + col;
            *(float2*)p = make_float2(acc[f][g][0], acc[f][g][1]);
            *(float2*)(p + 8 * (size_t)Nglob) = make_float2(acc[f][g][2], acc[f][g][3]);
        }
    }
}

// ---------------- elementwise h ----------------
__global__ void h_kernel(const float* __restrict__ usp, const float* __restrict__ vsp) {
    const float SQRT_D = 22.62741699796952f;
    int i4 = blockIdx.x * blockDim.x + threadIdx.x;
    if (i4 >= Mm * Ff / 4) return;
    int m  = i4 >> 8;
    int f  = (i4 & 255) * 4;
    int l  = m & 127;

    float4 u  = *(const float4*)(g_U   + (size_t)m * Ff + f);
    float4 v  = *(const float4*)(g_V   + (size_t)m * Ff + f);
    float4 ig = *(const float4*)(g_ing + (size_t)l * Ff + f);
    float4 iu = *(const float4*)(g_inu + (size_t)l * Ff + f);
    float4 us = *(const float4*)(usp + f);
    float4 vs = *(const float4*)(vsp + f);

    float4 h;
    { float uu = u.x * ig.x, vv = v.x * iu.x; float zz = fabsf(vs.x) * SQRT_D * vv;
      h.x = (zz / (1.f + expf(-zz))) * (fabsf(us.x) * uu); }
    { float uu = u.y * ig.y, vv = v.y * iu.y; float zz = fabsf(vs.y) * SQRT_D * vv;
      h.y = (zz / (1.f + expf(-zz))) * (fabsf(us.y) * uu); }
    { float uu = u.z * ig.z, vv = v.z * iu.z; float zz = fabsf(vs.z) * SQRT_D * vv;
      h.z = (zz / (1.f + expf(-zz))) * (fabsf(us.z) * uu); }
    { float uu = u.w * ig.w, vv = v.w * iu.w; float zz = fabsf(vs.w) * SQRT_D * vv;
      h.w = (zz / (1.f + expf(-zz))) * (fabsf(us.w) * uu); }
    *(float4*)(g_H + (size_t)m * Ff + f) = h;
}

// ---------------- final normalize ----------------
__global__ void out_kernel(float* __restrict__ out) {
    int m = blockIdx.x;
    int t = threadIdx.x;
    int l = m & 127;

    float4 o  = *(const float4*)(g_O   + (size_t)m * Dd + t * 4);
    float4 iv = *(const float4*)(g_ind + (size_t)l * Dd + t * 4);
    o.x *= iv.x; o.y *= iv.y; o.z *= iv.z; o.w *= iv.w;

    float ss = o.x*o.x + o.y*o.y + o.z*o.z + o.w*o.w;
#pragma unroll
    for (int off = 16; off > 0; off >>= 1)
        ss += __shfl_xor_sync(0xffffffffu, ss, off);

    __shared__ float ws[4];
    if ((t & 31) == 0) ws[t >> 5] = ss;
    __syncthreads();
    float tot = ws[0] + ws[1] + ws[2] + ws[3];
    float sc = 1.f / fmaxf(sqrtf(tot), 1e-12f);

    o.x *= sc; o.y *= sc; o.z *= sc; o.w *= sc;
    *(float4*)(out + (size_t)m * Dd + t * 4) = o;
}

// ---------------- launch ----------------
extern "C" void kernel_launch(void* const* d_in, const int* in_sizes, int n_in,
                              void* d_out, int out_size) {
    const float* x   = (const float*)d_in[0];
    const float* Wg  = (const float*)d_in[1];
    const float* Wu  = (const float*)d_in[2];
    const float* Wd  = (const float*)d_in[3];
    const float* t1  = (const float*)d_in[4];
    const float* t2  = (const float*)d_in[5];
    const float* t3  = (const float*)d_in[6];
    const float* usp = (const float*)d_in[7];
    const float* vsp = (const float*)d_in[8];
    float* out = (float*)d_out;

    softmax_kernel<<<3, 128>>>(t1, t2, t3);
    gram_kernel<<<dim3(32, 3), 256>>>(Wg, Wu, Wd);
    norm_kernel<<<dim3(8, Ll, 3), 128>>>();

    // U = (c1 . x) @ Wg   (Wg viewed as [8192, 1024])
    gemm3<128><<<dim3(8, 16), 256>>>(x, Wg, 0, 512, 9, 8192, 1024);
    // V = (c2 . x) @ Wu
    gemm3<128><<<dim3(8, 16), 256>>>(x, Wu, 1, 512, 9, 8192, 1024);
    // h = silu(vs*v) * (us*u)
    h_kernel<<<2048, 256>>>(usp, vsp);
    // O = (c3 . h) @ Wd   (Wd viewed as [16384, 512])
    gemm3<64><<<dim3(8, 16), 256>>>(nullptr, Wd, 2, 1024, 10, 16384, 512);
    // final
    out_kernel<<<2048, 128>>>(out);
}